// round 4
// baseline (speedup 1.0000x reference)
#include <cuda_runtime.h>
#include <cuda_bf16.h>
#include <math.h>
#include <stdint.h>

#define B_  4
#define S_  8192
#define D_  1024
#define NF_ 256
#define TWO_NF_ 512
#define M_  (B_*S_)

#define FIR_L 128
#define FIR_W 64

// smem tile pitch: 32 bf16 = 64B data + 16B pad -> conflict-free ldmatrix
#define PITCH 80
#define MAT_BYTES (128 * PITCH)          // 10240 per matrix (128 rows)
#define STAGE_BYTES (4 * MAT_BYTES)      // Ahi, Alo, Bhi, Blo
#define SMEM_TOTAL (2 * STAGE_BYTES)     // double buffer = 81920

// ------------------------------ scratch (device globals; no allocs) --------
__device__ __align__(16) float          g_spectral[(size_t)M_ * TWO_NF_];
__device__ __align__(16) unsigned short g_xhi[(size_t)M_ * D_];
__device__ __align__(16) unsigned short g_xlo[(size_t)M_ * D_];
__device__ __align__(16) unsigned short g_wih[(size_t)TWO_NF_ * D_];
__device__ __align__(16) unsigned short g_wil[(size_t)TWO_NF_ * D_];
__device__ __align__(16) unsigned short g_woh[(size_t)D_ * TWO_NF_];
__device__ __align__(16) unsigned short g_wol[(size_t)D_ * TWO_NF_];
__device__ __align__(16) unsigned short g_fhi[(size_t)M_ * TWO_NF_];
__device__ __align__(16) unsigned short g_flo[(size_t)M_ * TWO_NF_];

// ------------------------------ helpers ------------------------------------
__device__ __forceinline__ uint32_t smem_to_u32(const void* p) {
    uint32_t a;
    asm("{ .reg .u64 t; cvta.to.shared.u64 t, %1; cvt.u32.u64 %0, t; }"
        : "=r"(a) : "l"(p));
    return a;
}

__device__ __forceinline__ void cpa16(uint32_t s, const void* g) {
    asm volatile("cp.async.cg.shared.global [%0], [%1], 16;"
                 :: "r"(s), "l"(g));
}
#define CP_COMMIT()  asm volatile("cp.async.commit_group;" ::: "memory")
#define CP_WAIT1()   asm volatile("cp.async.wait_group 1;" ::: "memory")

__device__ __forceinline__ void ldsm4(uint32_t* r, uint32_t addr) {
    asm volatile("ldmatrix.sync.aligned.m8n8.x4.shared.b16 {%0,%1,%2,%3}, [%4];"
                 : "=r"(r[0]), "=r"(r[1]), "=r"(r[2]), "=r"(r[3]) : "r"(addr));
}

__device__ __forceinline__ void mma16816(float* d, const uint32_t* a,
                                         uint32_t b0, uint32_t b1) {
    asm volatile(
        "mma.sync.aligned.m16n8k16.row.col.f32.bf16.bf16.f32 "
        "{%0,%1,%2,%3}, {%4,%5,%6,%7}, {%8,%9}, {%0,%1,%2,%3};"
        : "+f"(d[0]), "+f"(d[1]), "+f"(d[2]), "+f"(d[3])
        : "r"(a[0]), "r"(a[1]), "r"(a[2]), "r"(a[3]), "r"(b0), "r"(b1));
}

// ---------------------------------------------------------------------------
// C[M,N] = A[M,K] * B[N,K]^T with bf16 hi/lo split operands.
// acc += Ahi*Bhi + Alo*Bhi + Ahi*Blo (fp32 accumulate), phase-separated so
// each accumulator quad is reused at distance >= 8 MMAs (no RAW chains).
// BM=128, BN=128, BK=32, 256 threads (8 warps, 4m x 2n, warp tile 32x64).
// ---------------------------------------------------------------------------
__global__ __launch_bounds__(256, 2)
void gemm_mma(const unsigned short* __restrict__ Ahi,
              const unsigned short* __restrict__ Alo,
              const unsigned short* __restrict__ Bhi,
              const unsigned short* __restrict__ Blo,
              float* __restrict__ C, int N, int K)
{
    extern __shared__ char smem[];
    const uint32_t sbase = smem_to_u32(smem);

    const int tid  = threadIdx.x;
    const int lane = tid & 31;
    const int wid  = tid >> 5;
    const int wm   = wid >> 1;      // 0..3  (m offset wm*32)
    const int wn   = wid & 1;       // 0..1  (n offset wn*64)
    const int bm = blockIdx.y * 128;
    const int bn = blockIdx.x * 128;
    const int nchunks = K >> 5;

    const uint32_t lm_off = (uint32_t)(lane & 15) * PITCH + (uint32_t)(lane >> 4) * 16;

    float acc[2][8][4];
#pragma unroll
    for (int i = 0; i < 2; i++)
#pragma unroll
        for (int j = 0; j < 8; j++)
#pragma unroll
            for (int k = 0; k < 4; k++) acc[i][j][k] = 0.0f;

    // ---- stage loader ----
    auto load_stage = [&](int c, int buf) {
        const uint32_t sb = sbase + buf * STAGE_BYTES;
        const int kofs = c * 32;
#pragma unroll
        for (int t = 0; t < 2; t++) {
            const int idx = tid + t * 256;
            const int r = idx >> 2;
            const int sg = idx & 3;
            const uint32_t so = (uint32_t)r * PITCH + sg * 16;
            const size_t ga = (size_t)(bm + r) * K + kofs + sg * 8;
            const size_t gb = (size_t)(bn + r) * K + kofs + sg * 8;
            cpa16(sb + 0 * MAT_BYTES + so, Ahi + ga);
            cpa16(sb + 1 * MAT_BYTES + so, Alo + ga);
            cpa16(sb + 2 * MAT_BYTES + so, Bhi + gb);
            cpa16(sb + 3 * MAT_BYTES + so, Blo + gb);
        }
    };

    load_stage(0, 0); CP_COMMIT();
    if (nchunks > 1) load_stage(1, 1);
    CP_COMMIT();

    for (int c = 0; c < nchunks; c++) {
        const int buf = c & 1;
        CP_WAIT1();
        __syncthreads();

        const uint32_t sb = sbase + buf * STAGE_BYTES;
        const uint32_t aBase = sb + (uint32_t)(wm * 32) * PITCH + lm_off;
        const uint32_t bBase = sb + 2 * MAT_BYTES + (uint32_t)(wn * 64) * PITCH + lm_off;

#pragma unroll
        for (int ks = 0; ks < 2; ks++) {
            const uint32_t ko = ks * 32;   // 16 bf16 = 32B

            uint32_t ah[2][4], al[2][4], bh[4][4];
#pragma unroll
            for (int mt = 0; mt < 2; mt++) {
                ldsm4(ah[mt], aBase + (uint32_t)(mt * 16) * PITCH + ko);
                ldsm4(al[mt], aBase + MAT_BYTES + (uint32_t)(mt * 16) * PITCH + ko);
            }
#pragma unroll
            for (int nt = 0; nt < 4; nt++)
                ldsm4(bh[nt], bBase + (uint32_t)(nt * 16) * PITCH + ko);

            // phase 1: hi * hi  (16 MMAs, all distinct accs)
#pragma unroll
            for (int nt = 0; nt < 4; nt++)
#pragma unroll
                for (int mt = 0; mt < 2; mt++) {
                    mma16816(acc[mt][2 * nt],     ah[mt], bh[nt][0], bh[nt][2]);
                    mma16816(acc[mt][2 * nt + 1], ah[mt], bh[nt][1], bh[nt][3]);
                }
            // phase 2: lo * hi  (reuse persistent bh)
#pragma unroll
            for (int nt = 0; nt < 4; nt++)
#pragma unroll
                for (int mt = 0; mt < 2; mt++) {
                    mma16816(acc[mt][2 * nt],     al[mt], bh[nt][0], bh[nt][2]);
                    mma16816(acc[mt][2 * nt + 1], al[mt], bh[nt][1], bh[nt][3]);
                }
            // phase 3: hi * lo  (bl transient, 4 regs)
#pragma unroll
            for (int nt = 0; nt < 4; nt++) {
                uint32_t bl[4];
                ldsm4(bl, bBase + MAT_BYTES + (uint32_t)(nt * 16) * PITCH + ko);
#pragma unroll
                for (int mt = 0; mt < 2; mt++) {
                    mma16816(acc[mt][2 * nt],     ah[mt], bl[0], bl[2]);
                    mma16816(acc[mt][2 * nt + 1], ah[mt], bl[1], bl[3]);
                }
            }
        }
        __syncthreads();
        if (c + 2 < nchunks) load_stage(c + 2, buf);
        CP_COMMIT();
    }

    // ---- epilogue ----
    const int r0 = bm + wm * 32 + (lane >> 2);
    const int c0 = bn + wn * 64 + (lane & 3) * 2;
#pragma unroll
    for (int mt = 0; mt < 2; mt++) {
#pragma unroll
        for (int nt = 0; nt < 8; nt++) {
            const int row = r0 + mt * 16;
            const int col = c0 + nt * 8;
            *(float2*)&C[(size_t)row * N + col] =
                make_float2(acc[mt][nt][0], acc[mt][nt][1]);
            *(float2*)&C[(size_t)(row + 8) * N + col] =
                make_float2(acc[mt][nt][2], acc[mt][nt][3]);
        }
    }
}

// ---------------------------------------------------------------------------
// fp32 -> bf16 hi/lo split
// ---------------------------------------------------------------------------
__device__ __forceinline__ void split1(float v, unsigned short& h, unsigned short& l) {
    __nv_bfloat16 hb = __float2bfloat16(v);
    float r = v - __bfloat162float(hb);
    __nv_bfloat16 lb = __float2bfloat16(r);
    h = __bfloat16_as_ushort(hb);
    l = __bfloat16_as_ushort(lb);
}

__global__ __launch_bounds__(256)
void split_kernel(const float* __restrict__ src,
                  unsigned short* __restrict__ hi,
                  unsigned short* __restrict__ lo, int n4)
{
    int i = blockIdx.x * blockDim.x + threadIdx.x;
    if (i >= n4) return;
    float4 v = ((const float4*)src)[i];
    ushort4 H, L;
    split1(v.x, H.x, L.x);
    split1(v.y, H.y, L.y);
    split1(v.z, H.z, L.z);
    split1(v.w, H.w, L.w);
    ((ushort4*)hi)[i] = H;
    ((ushort4*)lo)[i] = L;
}

// ---------------------------------------------------------------------------
// FIR: chunked exact linear recurrence h[t] = A*h[t-1] + u[t], y = rot*h.
// |A| = sigmoid(log_decay) < 0.5 -> 64-step warm-up makes chunks independent.
// Writes feats directly as bf16 hi/lo for GEMM2.
// ---------------------------------------------------------------------------
__global__ __launch_bounds__(NF_)
void fir_kernel(const float* __restrict__ spectral,
                const float* __restrict__ log_decay,
                const float* __restrict__ frequencies,
                unsigned short* __restrict__ fhi,
                unsigned short* __restrict__ flo)
{
    const int f = threadIdx.x;
    const int chunks_per_b = S_ / FIR_L;
    const int b = blockIdx.x / chunks_per_b;
    const int c = blockIdx.x % chunks_per_b;
    const int t_start = c * FIR_L;

    const float ld = log_decay[f];
    const float decay = 1.0f / (1.0f + expf(-ld));
    const float om = frequencies[f] * 0.1f;
    float si, co;
    sincosf(om, &si, &co);
    const float Ar = decay * co;
    const float Ai = decay * si;

    float hr = 0.0f, hi = 0.0f;
    int t0 = t_start - FIR_W;
    if (t0 < 0) t0 = 0;

    const size_t base = (size_t)b * S_ * TWO_NF_;

    for (int t = t0; t < t_start; t++) {               // warm-up
        const size_t row = base + (size_t)t * TWO_NF_;
        const float ur = spectral[row + f];
        const float ui = spectral[row + NF_ + f];
        const float nhr = fmaf(Ar, hr, fmaf(-Ai, hi, ur));
        const float nhi = fmaf(Ar, hi, fmaf(Ai, hr, ui));
        hr = nhr; hi = nhi;
    }
    for (int t = t_start; t < t_start + FIR_L; t++) {  // output
        const size_t row = base + (size_t)t * TWO_NF_;
        const float ur = spectral[row + f];
        const float ui = spectral[row + NF_ + f];
        const float nhr = fmaf(Ar, hr, fmaf(-Ai, hi, ur));
        const float nhi = fmaf(Ar, hi, fmaf(Ai, hr, ui));
        hr = nhr; hi = nhi;
        const float yr = fmaf(co, hr, -(si * hi));
        const float yi = fmaf(co, hi,  (si * hr));
        unsigned short h0, l0, h1, l1;
        split1(yr, h0, l0);
        split1(yi, h1, l1);
        fhi[row + f]       = h0;
        flo[row + f]       = l0;
        fhi[row + NF_ + f] = h1;
        flo[row + NF_ + f] = l1;
    }
}

// ---------------------------------------------------------------------------
extern "C" void kernel_launch(void* const* d_in, const int* in_sizes, int n_in,
                              void* d_out, int out_size) {
    const float* x     = (const float*)d_in[0];   // [B,S,D]
    const float* W_in  = (const float*)d_in[1];   // [2NF, D]
    const float* W_out = (const float*)d_in[2];   // [D, 2NF]
    const float* ldec  = (const float*)d_in[3];   // [NF]
    const float* freqs = (const float*)d_in[4];   // [NF]
    float* out = (float*)d_out;                   // [B,S,D]

    float* spectral = nullptr;
    unsigned short *xhi, *xlo, *wih, *wil, *woh, *wol, *fhi, *flo;
    cudaGetSymbolAddress((void**)&spectral, g_spectral);
    cudaGetSymbolAddress((void**)&xhi, g_xhi);
    cudaGetSymbolAddress((void**)&xlo, g_xlo);
    cudaGetSymbolAddress((void**)&wih, g_wih);
    cudaGetSymbolAddress((void**)&wil, g_wil);
    cudaGetSymbolAddress((void**)&woh, g_woh);
    cudaGetSymbolAddress((void**)&wol, g_wol);
    cudaGetSymbolAddress((void**)&fhi, g_fhi);
    cudaGetSymbolAddress((void**)&flo, g_flo);

    cudaFuncSetAttribute(gemm_mma, cudaFuncAttributeMaxDynamicSharedMemorySize,
                         SMEM_TOTAL);

    // 1) hi/lo splits
    {
        int n4 = (M_ * D_) / 4;
        split_kernel<<<n4 / 256, 256>>>(x, xhi, xlo, n4);
    }
    {
        int n4 = (TWO_NF_ * D_) / 4;
        split_kernel<<<(n4 + 255) / 256, 256>>>(W_in, wih, wil, n4);
        split_kernel<<<(n4 + 255) / 256, 256>>>(W_out, woh, wol, n4);
    }

    // 2) GEMM1: spectral[M, 512] = x[M,1024] @ W_in[512,1024]^T
    {
        dim3 grid(TWO_NF_ / 128, M_ / 128);
        gemm_mma<<<grid, 256, SMEM_TOTAL>>>(xhi, xlo, wih, wil,
                                            spectral, TWO_NF_, D_);
    }

    // 3) FIR scan -> feats (bf16 hi/lo)
    {
        dim3 grid(B_ * (S_ / FIR_L));
        fir_kernel<<<grid, NF_>>>(spectral, ldec, freqs, fhi, flo);
    }

    // 4) GEMM2: out[M, 1024] = feats[M,512] @ W_out[1024,512]^T
    {
        dim3 grid(D_ / 128, M_ / 128);
        gemm_mma<<<grid, 256, SMEM_TOTAL>>>(fhi, flo, woh, wol,
                                            out, D_, TWO_NF_);
    }
}

// round 5
// speedup vs baseline: 1.3323x; 1.3323x over previous
#include <cuda_runtime.h>
#include <cuda_fp16.h>
#include <math.h>
#include <stdint.h>

#define B_  4
#define S_  8192
#define D_  1024
#define NF_ 256
#define TWO_NF_ 512
#define M_  (B_*S_)

#define FIR_L 128
#define FIR_W 64

// smem tile pitch: 32 fp16 = 64B data + 16B pad -> conflict-free ldmatrix
#define PITCH 80
#define MAT_BYTES (128 * PITCH)          // 10240 per matrix (128 rows)
#define STAGE_BYTES (3 * MAT_BYTES)      // Ahi, Alo, Bhi
#define SMEM_TOTAL (2 * STAGE_BYTES)     // double buffer = 61440

// ------------------------------ scratch (device globals; no allocs) --------
__device__ __align__(16) float          g_spectral[(size_t)M_ * TWO_NF_];
__device__ __align__(16) unsigned short g_xhi[(size_t)M_ * D_];
__device__ __align__(16) unsigned short g_xlo[(size_t)M_ * D_];
__device__ __align__(16) unsigned short g_wih[(size_t)TWO_NF_ * D_];   // fp16(W_in)
__device__ __align__(16) unsigned short g_woh[(size_t)D_ * TWO_NF_];   // fp16(W_out)
__device__ __align__(16) unsigned short g_fhi[(size_t)M_ * TWO_NF_];
__device__ __align__(16) unsigned short g_flo[(size_t)M_ * TWO_NF_];

// ------------------------------ helpers ------------------------------------
__device__ __forceinline__ uint32_t smem_to_u32(const void* p) {
    uint32_t a;
    asm("{ .reg .u64 t; cvta.to.shared.u64 t, %1; cvt.u32.u64 %0, t; }"
        : "=r"(a) : "l"(p));
    return a;
}

__device__ __forceinline__ void cpa16(uint32_t s, const void* g) {
    asm volatile("cp.async.cg.shared.global [%0], [%1], 16;"
                 :: "r"(s), "l"(g));
}
#define CP_COMMIT()  asm volatile("cp.async.commit_group;" ::: "memory")
#define CP_WAIT1()   asm volatile("cp.async.wait_group 1;" ::: "memory")

__device__ __forceinline__ void ldsm4(uint32_t* r, uint32_t addr) {
    asm volatile("ldmatrix.sync.aligned.m8n8.x4.shared.b16 {%0,%1,%2,%3}, [%4];"
                 : "=r"(r[0]), "=r"(r[1]), "=r"(r[2]), "=r"(r[3]) : "r"(addr));
}

__device__ __forceinline__ void mma16816(float* d, const uint32_t* a,
                                         uint32_t b0, uint32_t b1) {
    asm volatile(
        "mma.sync.aligned.m16n8k16.row.col.f32.f16.f16.f32 "
        "{%0,%1,%2,%3}, {%4,%5,%6,%7}, {%8,%9}, {%0,%1,%2,%3};"
        : "+f"(d[0]), "+f"(d[1]), "+f"(d[2]), "+f"(d[3])
        : "r"(a[0]), "r"(a[1]), "r"(a[2]), "r"(a[3]), "r"(b0), "r"(b1));
}

// ---------------------------------------------------------------------------
// C[M,N] = A[M,K] * B[N,K]^T, fp16 2-term split: (Ahi + Alo) * Bhi, fp32 acc.
// BM=128, BN=128, BK=32, 256 threads (8 warps, 4m x 2n, warp tile 32x64).
// ---------------------------------------------------------------------------
__global__ __launch_bounds__(256, 2)
void gemm_mma(const unsigned short* __restrict__ Ahi,
              const unsigned short* __restrict__ Alo,
              const unsigned short* __restrict__ Bh,
              float* __restrict__ C, int N, int K)
{
    extern __shared__ char smem[];
    const uint32_t sbase = smem_to_u32(smem);

    const int tid  = threadIdx.x;
    const int lane = tid & 31;
    const int wid  = tid >> 5;
    const int wm   = wid >> 1;      // 0..3  (m offset wm*32)
    const int wn   = wid & 1;       // 0..1  (n offset wn*64)
    const int bm = blockIdx.y * 128;
    const int bn = blockIdx.x * 128;
    const int nchunks = K >> 5;

    const uint32_t lm_off = (uint32_t)(lane & 15) * PITCH + (uint32_t)(lane >> 4) * 16;

    float acc[2][8][4];
#pragma unroll
    for (int i = 0; i < 2; i++)
#pragma unroll
        for (int j = 0; j < 8; j++)
#pragma unroll
            for (int k = 0; k < 4; k++) acc[i][j][k] = 0.0f;

    // ---- stage loader: 3 matrices (Ahi, Alo, Bhi), 6 cp.async / thread ----
    auto load_stage = [&](int c, int buf) {
        const uint32_t sb = sbase + buf * STAGE_BYTES;
        const int kofs = c * 32;
#pragma unroll
        for (int t = 0; t < 2; t++) {
            const int idx = tid + t * 256;
            const int r = idx >> 2;
            const int sg = idx & 3;
            const uint32_t so = (uint32_t)r * PITCH + sg * 16;
            const size_t ga = (size_t)(bm + r) * K + kofs + sg * 8;
            const size_t gb = (size_t)(bn + r) * K + kofs + sg * 8;
            cpa16(sb + 0 * MAT_BYTES + so, Ahi + ga);
            cpa16(sb + 1 * MAT_BYTES + so, Alo + ga);
            cpa16(sb + 2 * MAT_BYTES + so, Bh + gb);
        }
    };

    load_stage(0, 0); CP_COMMIT();
    if (nchunks > 1) load_stage(1, 1);
    CP_COMMIT();

    for (int c = 0; c < nchunks; c++) {
        const int buf = c & 1;
        CP_WAIT1();
        __syncthreads();

        const uint32_t sb = sbase + buf * STAGE_BYTES;
        const uint32_t aBase = sb + (uint32_t)(wm * 32) * PITCH + lm_off;
        const uint32_t bBase = sb + 2 * MAT_BYTES + (uint32_t)(wn * 64) * PITCH + lm_off;

#pragma unroll
        for (int ks = 0; ks < 2; ks++) {
            const uint32_t ko = ks * 32;   // 16 fp16 = 32B

            uint32_t ah[2][4], al[2][4], bh[4][4];
#pragma unroll
            for (int mt = 0; mt < 2; mt++) {
                ldsm4(ah[mt], aBase + (uint32_t)(mt * 16) * PITCH + ko);
                ldsm4(al[mt], aBase + MAT_BYTES + (uint32_t)(mt * 16) * PITCH + ko);
            }
#pragma unroll
            for (int nt = 0; nt < 4; nt++)
                ldsm4(bh[nt], bBase + (uint32_t)(nt * 16) * PITCH + ko);

            // phase 1: hi * hi
#pragma unroll
            for (int nt = 0; nt < 4; nt++)
#pragma unroll
                for (int mt = 0; mt < 2; mt++) {
                    mma16816(acc[mt][2 * nt],     ah[mt], bh[nt][0], bh[nt][2]);
                    mma16816(acc[mt][2 * nt + 1], ah[mt], bh[nt][1], bh[nt][3]);
                }
            // phase 2: lo * hi
#pragma unroll
            for (int nt = 0; nt < 4; nt++)
#pragma unroll
                for (int mt = 0; mt < 2; mt++) {
                    mma16816(acc[mt][2 * nt],     al[mt], bh[nt][0], bh[nt][2]);
                    mma16816(acc[mt][2 * nt + 1], al[mt], bh[nt][1], bh[nt][3]);
                }
        }
        __syncthreads();
        if (c + 2 < nchunks) load_stage(c + 2, buf);
        CP_COMMIT();
    }

    // ---- epilogue ----
    const int r0 = bm + wm * 32 + (lane >> 2);
    const int c0 = bn + wn * 64 + (lane & 3) * 2;
#pragma unroll
    for (int mt = 0; mt < 2; mt++) {
#pragma unroll
        for (int nt = 0; nt < 8; nt++) {
            const int row = r0 + mt * 16;
            const int col = c0 + nt * 8;
            *(float2*)&C[(size_t)row * N + col] =
                make_float2(acc[mt][nt][0], acc[mt][nt][1]);
            *(float2*)&C[(size_t)(row + 8) * N + col] =
                make_float2(acc[mt][nt][2], acc[mt][nt][3]);
        }
    }
}

// ---------------------------------------------------------------------------
// fp32 -> fp16 hi/lo split (A-side operands)
// ---------------------------------------------------------------------------
__device__ __forceinline__ void split1(float v, unsigned short& h, unsigned short& l) {
    __half hh = __float2half_rn(v);
    float r = v - __half2float(hh);
    __half ll = __float2half_rn(r);
    h = __half_as_ushort(hh);
    l = __half_as_ushort(ll);
}

__global__ __launch_bounds__(256)
void split_kernel(const float* __restrict__ src,
                  unsigned short* __restrict__ hi,
                  unsigned short* __restrict__ lo, int n4)
{
    int i = blockIdx.x * blockDim.x + threadIdx.x;
    if (i >= n4) return;
    float4 v = ((const float4*)src)[i];
    ushort4 H, L;
    split1(v.x, H.x, L.x);
    split1(v.y, H.y, L.y);
    split1(v.z, H.z, L.z);
    split1(v.w, H.w, L.w);
    ((ushort4*)hi)[i] = H;
    ((ushort4*)lo)[i] = L;
}

// fp32 -> fp16 plain convert (B-side operands)
__global__ __launch_bounds__(256)
void cvt_kernel(const float* __restrict__ src,
                unsigned short* __restrict__ dst, int n4)
{
    int i = blockIdx.x * blockDim.x + threadIdx.x;
    if (i >= n4) return;
    float4 v = ((const float4*)src)[i];
    ushort4 H;
    H.x = __half_as_ushort(__float2half_rn(v.x));
    H.y = __half_as_ushort(__float2half_rn(v.y));
    H.z = __half_as_ushort(__float2half_rn(v.z));
    H.w = __half_as_ushort(__float2half_rn(v.w));
    ((ushort4*)dst)[i] = H;
}

// ---------------------------------------------------------------------------
// FIR: chunked exact linear recurrence h[t] = A*h[t-1] + u[t], y = rot*h.
// |A| = sigmoid(log_decay) < 0.5 -> 64-step warm-up makes chunks independent.
// Writes feats directly as fp16 hi/lo for GEMM2.
// ---------------------------------------------------------------------------
__global__ __launch_bounds__(NF_)
void fir_kernel(const float* __restrict__ spectral,
                const float* __restrict__ log_decay,
                const float* __restrict__ frequencies,
                unsigned short* __restrict__ fhi,
                unsigned short* __restrict__ flo)
{
    const int f = threadIdx.x;
    const int chunks_per_b = S_ / FIR_L;
    const int b = blockIdx.x / chunks_per_b;
    const int c = blockIdx.x % chunks_per_b;
    const int t_start = c * FIR_L;

    const float ld = log_decay[f];
    const float decay = 1.0f / (1.0f + expf(-ld));
    const float om = frequencies[f] * 0.1f;
    float si, co;
    sincosf(om, &si, &co);
    const float Ar = decay * co;
    const float Ai = decay * si;

    float hr = 0.0f, hi = 0.0f;
    int t0 = t_start - FIR_W;
    if (t0 < 0) t0 = 0;

    const size_t base = (size_t)b * S_ * TWO_NF_;

    for (int t = t0; t < t_start; t++) {               // warm-up
        const size_t row = base + (size_t)t * TWO_NF_;
        const float ur = spectral[row + f];
        const float ui = spectral[row + NF_ + f];
        const float nhr = fmaf(Ar, hr, fmaf(-Ai, hi, ur));
        const float nhi = fmaf(Ar, hi, fmaf(Ai, hr, ui));
        hr = nhr; hi = nhi;
    }
    for (int t = t_start; t < t_start + FIR_L; t++) {  // output
        const size_t row = base + (size_t)t * TWO_NF_;
        const float ur = spectral[row + f];
        const float ui = spectral[row + NF_ + f];
        const float nhr = fmaf(Ar, hr, fmaf(-Ai, hi, ur));
        const float nhi = fmaf(Ar, hi, fmaf(Ai, hr, ui));
        hr = nhr; hi = nhi;
        const float yr = fmaf(co, hr, -(si * hi));
        const float yi = fmaf(co, hi,  (si * hr));
        unsigned short h0, l0, h1, l1;
        split1(yr, h0, l0);
        split1(yi, h1, l1);
        fhi[row + f]       = h0;
        flo[row + f]       = l0;
        fhi[row + NF_ + f] = h1;
        flo[row + NF_ + f] = l1;
    }
}

// ---------------------------------------------------------------------------
extern "C" void kernel_launch(void* const* d_in, const int* in_sizes, int n_in,
                              void* d_out, int out_size) {
    const float* x     = (const float*)d_in[0];   // [B,S,D]
    const float* W_in  = (const float*)d_in[1];   // [2NF, D]
    const float* W_out = (const float*)d_in[2];   // [D, 2NF]
    const float* ldec  = (const float*)d_in[3];   // [NF]
    const float* freqs = (const float*)d_in[4];   // [NF]
    float* out = (float*)d_out;                   // [B,S,D]

    float* spectral = nullptr;
    unsigned short *xhi, *xlo, *wih, *woh, *fhi, *flo;
    cudaGetSymbolAddress((void**)&spectral, g_spectral);
    cudaGetSymbolAddress((void**)&xhi, g_xhi);
    cudaGetSymbolAddress((void**)&xlo, g_xlo);
    cudaGetSymbolAddress((void**)&wih, g_wih);
    cudaGetSymbolAddress((void**)&woh, g_woh);
    cudaGetSymbolAddress((void**)&fhi, g_fhi);
    cudaGetSymbolAddress((void**)&flo, g_flo);

    cudaFuncSetAttribute(gemm_mma, cudaFuncAttributeMaxDynamicSharedMemorySize,
                         SMEM_TOTAL);

    // 1) conversions: x -> fp16 hi/lo split; weights -> fp16
    {
        int n4 = (M_ * D_) / 4;
        split_kernel<<<n4 / 256, 256>>>(x, xhi, xlo, n4);
    }
    {
        int n4 = (TWO_NF_ * D_) / 4;
        cvt_kernel<<<(n4 + 255) / 256, 256>>>(W_in, wih, n4);
        cvt_kernel<<<(n4 + 255) / 256, 256>>>(W_out, woh, n4);
    }

    // 2) GEMM1: spectral[M, 512] = x[M,1024] @ W_in[512,1024]^T
    {
        dim3 grid(TWO_NF_ / 128, M_ / 128);
        gemm_mma<<<grid, 256, SMEM_TOTAL>>>(xhi, xlo, wih,
                                            spectral, TWO_NF_, D_);
    }

    // 3) FIR scan -> feats (fp16 hi/lo)
    {
        dim3 grid(B_ * (S_ / FIR_L));
        fir_kernel<<<grid, NF_>>>(spectral, ldec, freqs, fhi, flo);
    }

    // 4) GEMM2: out[M, 1024] = feats[M,512] @ W_out[1024,512]^T
    {
        dim3 grid(D_ / 128, M_ / 128);
        gemm_mma<<<grid, 256, SMEM_TOTAL>>>(fhi, flo, woh,
                                            out, D_, TWO_NF_);
    }
}

// round 6
// speedup vs baseline: 2.2674x; 1.7018x over previous
#include <cuda_runtime.h>
#include <cuda_fp16.h>
#include <math.h>
#include <stdint.h>

#define B_  4
#define S_  8192
#define D_  1024
#define NF_ 256
#define TWO_NF_ 512
#define M_  (B_*S_)

#define FIR_L 128
#define FIR_W 64

// smem tile pitch: 32 fp16 = 64B data + 16B pad -> conflict-free ldmatrix
#define PITCH 80
#define MAT_BYTES (128 * PITCH)          // 10240 per matrix (128 rows)
#define STAGE_BYTES (2 * MAT_BYTES)      // A, B
#define SMEM_TOTAL (2 * STAGE_BYTES)     // double buffer = 40960

// ------------------------------ scratch (device globals; no allocs) --------
__device__ __align__(16) float          g_spectral[(size_t)M_ * TWO_NF_];
__device__ __align__(16) unsigned short g_xh[(size_t)M_ * D_];         // fp16(x)
__device__ __align__(16) unsigned short g_wih[(size_t)TWO_NF_ * D_];   // fp16(W_in)
__device__ __align__(16) unsigned short g_woh[(size_t)D_ * TWO_NF_];   // fp16(W_out)
__device__ __align__(16) unsigned short g_fh[(size_t)M_ * TWO_NF_];    // fp16(feats)

// ------------------------------ helpers ------------------------------------
__device__ __forceinline__ uint32_t smem_to_u32(const void* p) {
    uint32_t a;
    asm("{ .reg .u64 t; cvta.to.shared.u64 t, %1; cvt.u32.u64 %0, t; }"
        : "=r"(a) : "l"(p));
    return a;
}

__device__ __forceinline__ void cpa16(uint32_t s, const void* g) {
    asm volatile("cp.async.cg.shared.global [%0], [%1], 16;"
                 :: "r"(s), "l"(g));
}
#define CP_COMMIT()  asm volatile("cp.async.commit_group;" ::: "memory")
#define CP_WAIT1()   asm volatile("cp.async.wait_group 1;" ::: "memory")

__device__ __forceinline__ void ldsm4(uint32_t* r, uint32_t addr) {
    asm volatile("ldmatrix.sync.aligned.m8n8.x4.shared.b16 {%0,%1,%2,%3}, [%4];"
                 : "=r"(r[0]), "=r"(r[1]), "=r"(r[2]), "=r"(r[3]) : "r"(addr));
}

__device__ __forceinline__ void mma16816(float* d, const uint32_t* a,
                                         uint32_t b0, uint32_t b1) {
    asm volatile(
        "mma.sync.aligned.m16n8k16.row.col.f32.f16.f16.f32 "
        "{%0,%1,%2,%3}, {%4,%5,%6,%7}, {%8,%9}, {%0,%1,%2,%3};"
        : "+f"(d[0]), "+f"(d[1]), "+f"(d[2]), "+f"(d[3])
        : "r"(a[0]), "r"(a[1]), "r"(a[2]), "r"(a[3]), "r"(b0), "r"(b1));
}

// ---------------------------------------------------------------------------
// C[M,N] = A[M,K] * B[N,K]^T, fp16 operands, fp32 accumulate.
// BM=128, BN=128, BK=32, 256 threads (8 warps, 4m x 2n, warp tile 32x64).
// ---------------------------------------------------------------------------
__global__ __launch_bounds__(256, 2)
void gemm_mma(const unsigned short* __restrict__ Ah,
              const unsigned short* __restrict__ Bh,
              float* __restrict__ C, int N, int K)
{
    extern __shared__ char smem[];
    const uint32_t sbase = smem_to_u32(smem);

    const int tid  = threadIdx.x;
    const int lane = tid & 31;
    const int wid  = tid >> 5;
    const int wm   = wid >> 1;      // 0..3  (m offset wm*32)
    const int wn   = wid & 1;       // 0..1  (n offset wn*64)
    const int bm = blockIdx.y * 128;
    const int bn = blockIdx.x * 128;
    const int nchunks = K >> 5;

    const uint32_t lm_off = (uint32_t)(lane & 15) * PITCH + (uint32_t)(lane >> 4) * 16;

    float acc[2][8][4];
#pragma unroll
    for (int i = 0; i < 2; i++)
#pragma unroll
        for (int j = 0; j < 8; j++)
#pragma unroll
            for (int k = 0; k < 4; k++) acc[i][j][k] = 0.0f;

    // ---- stage loader: 2 matrices (A, B), 4 cp.async / thread ----
    auto load_stage = [&](int c, int buf) {
        const uint32_t sb = sbase + buf * STAGE_BYTES;
        const int kofs = c * 32;
#pragma unroll
        for (int t = 0; t < 2; t++) {
            const int idx = tid + t * 256;
            const int r = idx >> 2;
            const int sg = idx & 3;
            const uint32_t so = (uint32_t)r * PITCH + sg * 16;
            const size_t ga = (size_t)(bm + r) * K + kofs + sg * 8;
            const size_t gb = (size_t)(bn + r) * K + kofs + sg * 8;
            cpa16(sb + 0 * MAT_BYTES + so, Ah + ga);
            cpa16(sb + 1 * MAT_BYTES + so, Bh + gb);
        }
    };

    load_stage(0, 0); CP_COMMIT();
    if (nchunks > 1) load_stage(1, 1);
    CP_COMMIT();

    for (int c = 0; c < nchunks; c++) {
        const int buf = c & 1;
        CP_WAIT1();
        __syncthreads();

        const uint32_t sb = sbase + buf * STAGE_BYTES;
        const uint32_t aBase = sb + (uint32_t)(wm * 32) * PITCH + lm_off;
        const uint32_t bBase = sb + MAT_BYTES + (uint32_t)(wn * 64) * PITCH + lm_off;

#pragma unroll
        for (int ks = 0; ks < 2; ks++) {
            const uint32_t ko = ks * 32;   // 16 fp16 = 32B

            uint32_t ah[2][4], bh[4][4];
#pragma unroll
            for (int mt = 0; mt < 2; mt++)
                ldsm4(ah[mt], aBase + (uint32_t)(mt * 16) * PITCH + ko);
#pragma unroll
            for (int nt = 0; nt < 4; nt++)
                ldsm4(bh[nt], bBase + (uint32_t)(nt * 16) * PITCH + ko);

#pragma unroll
            for (int nt = 0; nt < 4; nt++)
#pragma unroll
                for (int mt = 0; mt < 2; mt++) {
                    mma16816(acc[mt][2 * nt],     ah[mt], bh[nt][0], bh[nt][2]);
                    mma16816(acc[mt][2 * nt + 1], ah[mt], bh[nt][1], bh[nt][3]);
                }
        }
        __syncthreads();
        if (c + 2 < nchunks) load_stage(c + 2, buf);
        CP_COMMIT();
    }

    // ---- epilogue ----
    const int r0 = bm + wm * 32 + (lane >> 2);
    const int c0 = bn + wn * 64 + (lane & 3) * 2;
#pragma unroll
    for (int mt = 0; mt < 2; mt++) {
#pragma unroll
        for (int nt = 0; nt < 8; nt++) {
            const int row = r0 + mt * 16;
            const int col = c0 + nt * 8;
            *(float2*)&C[(size_t)row * N + col] =
                make_float2(acc[mt][nt][0], acc[mt][nt][1]);
            *(float2*)&C[(size_t)(row + 8) * N + col] =
                make_float2(acc[mt][nt][2], acc[mt][nt][3]);
        }
    }
}

// ---------------------------------------------------------------------------
// fp32 -> fp16 convert (vectorized)
// ---------------------------------------------------------------------------
__global__ __launch_bounds__(256)
void cvt_kernel(const float* __restrict__ src,
                unsigned short* __restrict__ dst, int n4)
{
    int i = blockIdx.x * blockDim.x + threadIdx.x;
    if (i >= n4) return;
    float4 v = ((const float4*)src)[i];
    ushort4 H;
    H.x = __half_as_ushort(__float2half_rn(v.x));
    H.y = __half_as_ushort(__float2half_rn(v.y));
    H.z = __half_as_ushort(__float2half_rn(v.z));
    H.w = __half_as_ushort(__float2half_rn(v.w));
    ((ushort4*)dst)[i] = H;
}

// ---------------------------------------------------------------------------
// FIR: chunked exact linear recurrence h[t] = A*h[t-1] + u[t], y = rot*h.
// |A| = sigmoid(log_decay) < 0.5 -> 64-step warm-up makes chunks independent.
// Writes feats as fp16 for GEMM2.
// ---------------------------------------------------------------------------
__global__ __launch_bounds__(NF_)
void fir_kernel(const float* __restrict__ spectral,
                const float* __restrict__ log_decay,
                const float* __restrict__ frequencies,
                unsigned short* __restrict__ fh)
{
    const int f = threadIdx.x;
    const int chunks_per_b = S_ / FIR_L;
    const int b = blockIdx.x / chunks_per_b;
    const int c = blockIdx.x % chunks_per_b;
    const int t_start = c * FIR_L;

    const float ld = log_decay[f];
    const float decay = 1.0f / (1.0f + expf(-ld));
    const float om = frequencies[f] * 0.1f;
    float si, co;
    sincosf(om, &si, &co);
    const float Ar = decay * co;
    const float Ai = decay * si;

    float hr = 0.0f, hi = 0.0f;
    int t0 = t_start - FIR_W;
    if (t0 < 0) t0 = 0;

    const size_t base = (size_t)b * S_ * TWO_NF_;

    for (int t = t0; t < t_start; t++) {               // warm-up
        const size_t row = base + (size_t)t * TWO_NF_;
        const float ur = spectral[row + f];
        const float ui = spectral[row + NF_ + f];
        const float nhr = fmaf(Ar, hr, fmaf(-Ai, hi, ur));
        const float nhi = fmaf(Ar, hi, fmaf(Ai, hr, ui));
        hr = nhr; hi = nhi;
    }
    for (int t = t_start; t < t_start + FIR_L; t++) {  // output
        const size_t row = base + (size_t)t * TWO_NF_;
        const float ur = spectral[row + f];
        const float ui = spectral[row + NF_ + f];
        const float nhr = fmaf(Ar, hr, fmaf(-Ai, hi, ur));
        const float nhi = fmaf(Ar, hi, fmaf(Ai, hr, ui));
        hr = nhr; hi = nhi;
        const float yr = fmaf(co, hr, -(si * hi));
        const float yi = fmaf(co, hi,  (si * hr));
        fh[row + f]       = __half_as_ushort(__float2half_rn(yr));
        fh[row + NF_ + f] = __half_as_ushort(__float2half_rn(yi));
    }
}

// ---------------------------------------------------------------------------
extern "C" void kernel_launch(void* const* d_in, const int* in_sizes, int n_in,
                              void* d_out, int out_size) {
    const float* x     = (const float*)d_in[0];   // [B,S,D]
    const float* W_in  = (const float*)d_in[1];   // [2NF, D]
    const float* W_out = (const float*)d_in[2];   // [D, 2NF]
    const float* ldec  = (const float*)d_in[3];   // [NF]
    const float* freqs = (const float*)d_in[4];   // [NF]
    float* out = (float*)d_out;                   // [B,S,D]

    float* spectral = nullptr;
    unsigned short *xh, *wih, *woh, *fh;
    cudaGetSymbolAddress((void**)&spectral, g_spectral);
    cudaGetSymbolAddress((void**)&xh, g_xh);
    cudaGetSymbolAddress((void**)&wih, g_wih);
    cudaGetSymbolAddress((void**)&woh, g_woh);
    cudaGetSymbolAddress((void**)&fh, g_fh);

    cudaFuncSetAttribute(gemm_mma, cudaFuncAttributeMaxDynamicSharedMemorySize,
                         SMEM_TOTAL);

    // 1) conversions to fp16
    {
        int n4 = (M_ * D_) / 4;
        cvt_kernel<<<n4 / 256, 256>>>(x, xh, n4);
    }
    {
        int n4 = (TWO_NF_ * D_) / 4;
        cvt_kernel<<<(n4 + 255) / 256, 256>>>(W_in, wih, n4);
        cvt_kernel<<<(n4 + 255) / 256, 256>>>(W_out, woh, n4);
    }

    // 2) GEMM1: spectral[M, 512] = x[M,1024] @ W_in[512,1024]^T
    {
        dim3 grid(TWO_NF_ / 128, M_ / 128);
        gemm_mma<<<grid, 256, SMEM_TOTAL>>>(xh, wih, spectral, TWO_NF_, D_);
    }

    // 3) FIR scan -> feats (fp16)
    {
        dim3 grid(B_ * (S_ / FIR_L));
        fir_kernel<<<grid, NF_>>>(spectral, ldec, freqs, fh);
    }

    // 4) GEMM2: out[M, 1024] = feats[M,512] @ W_out[1024,512]^T
    {
        dim3 grid(D_ / 128, M_ / 128);
        gemm_mma<<<grid, 256, SMEM_TOTAL>>>(fh, woh, out, D_, TWO_NF_);
    }
}